// round 17
// baseline (speedup 1.0000x reference)
#include <cuda_runtime.h>
#include <math.h>

// LambdaRankLoss: B=32, N=1024 -> scalar mean loss. Two kernels.
//
// Identity: softplus(-y_ij*s_ij)*log2e = lg2(e_i + e_j) - s'_hi
//   where e = 2^(s*log2e), s' = lg2(e), hi = higher-gain item.
// Items bucketed by label (5 buckets, descending in memory). Cross-bucket
// rectangles have constant |dgain| (applied at reduce) and constant select
// side -> inner loop = 5 fma-pipe ops + 1 MUFU per pair. Same-label pairs
// never enumerated. Sentinels give EXACT zero contribution:
//   row pad/masked: e = 2^100 -> t = lg2(2^100+ec) - 100 = 0
//   col pad/masked: e = 0     -> t = lg2(er) - s'r = 0 (same instr, same input)
// k_pairs: grid (20, B) = 640 blocks; 2 blocks per (bucket-pair, batch)
// rectangle, splitting row tiles (i % 2 == rq) -> ~4 blocks/SM occupancy.
// Each block stages both buckets once, register accumulators across tiles,
// one warp-reduce + atomic. No inter-block waits anywhere (deadlock-free).
// item_mask arrives as int32 (bool marshaled 4-byte).

#define NMAX 1024
#define BMAX 32
#define E_HI 1.2676506002282294e30f   // 2^100
#define S_HI 100.0f                   // lg2(E_HI)
#define MAXPAD 1152                   // 1024 rounded up one tile

__device__ float2 g_IT[BMAX * NMAX];  // bucketed items {e (0 if masked), d}
__device__ int    g_CNT[BMAX * 8];
__device__ int    g_OFF[BMAX * 8];
__device__ float  g_SUM[BMAX];
__device__ float  g_IDCG[BMAX];
__device__ int    g_FILL[BMAX * 5];   // scatter fill counters (reset at finalize)
__device__ int    g_FIN;

__device__ __forceinline__ float lg2af(float x) {
    float r; asm("lg2.approx.ftz.f32 %0, %1;" : "=f"(r) : "f"(x)); return r;
}

// grid (B, 8), block 256: 128 items/block, 2 threads/item split the compare
// range. Rank = 1 + #greater (tie-free data). Scatter into label buckets.
__global__ void __launch_bounds__(256) k_prep(const float* __restrict__ logits,
                                              const float* __restrict__ labels,
                                              const int* __restrict__ mask) {
    __shared__ __align__(16) float s_sh[NMAX];
    __shared__ int   hist[5];
    __shared__ int   c_sh[128];
    __shared__ float red[8];

    int b = blockIdx.x, chunk = blockIdx.y, tid = threadIdx.x;
    const float* sc = logits + b * NMAX;
    const float* lb = labels + b * NMAX;

    ((float4*)s_sh)[tid] = ((const float4*)sc)[tid];
    if (tid < 5) hist[tid] = 0;
    __syncthreads();

#pragma unroll
    for (int r = 0; r < 4; r++) {
        int l = (int)lb[tid + r * 256];
        atomicAdd(&hist[min(max(l, 0), 4)], 1);
    }
    __syncthreads();

    int off[5];
    off[4] = 0;
    off[3] = hist[4];
    off[2] = off[3] + hist[3];
    off[1] = off[2] + hist[2];
    off[0] = off[1] + hist[1];

    int item = chunk * 128 + (tid & 127);
    int half = tid >> 7;
    float si = s_sh[item];

    int cnt = 0;
    const float4* s4 = (const float4*)s_sh;
    int q0 = half * 128;
#pragma unroll 4
    for (int q = q0; q < q0 + 128; q++) {
        float4 v = s4[q];
        cnt += (v.x > si) + (v.y > si) + (v.z > si) + (v.w > si);
    }
    if (half == 0) c_sh[tid] = cnt;
    __syncthreads();
    if (half == 1) {
        int rank = cnt + c_sh[tid - 128] + 1;
        int l = (int)lb[item];
        l = min(max(l, 0), 4);
        float e = 0.0f;
        if (mask[b * NMAX + item] != 0)
            e = exp2f(si * 1.4426950408889634f);
        float d = __fdividef(1.0f, __log2f((float)(rank + 1)));
        int slot = off[l] + atomicAdd(&g_FILL[b * 5 + l], 1);
        g_IT[b * NMAX + slot] = make_float2(e, d);
    }

    if (chunk == 0) {
        if (tid < 5) { g_CNT[b * 8 + tid] = hist[tid]; g_OFF[b * 8 + tid] = off[tid]; }
        int e4 = hist[4];
        int e3 = e4 + hist[3];
        int e2 = e3 + hist[2];
        int e1 = e2 + hist[1];
        float part = 0.0f;
        for (int p = tid + 1; p <= NMAX; p += 256) {
            float disc = __fdividef(1.0f, __log2f((float)(p + 1)));
            float gn = (p <= e4) ? 15.f : (p <= e3) ? 7.f
                     : (p <= e2) ? 3.f  : (p <= e1) ? 1.f : 0.f;
            part += disc * gn;
        }
#pragma unroll
        for (int o = 16; o > 0; o >>= 1) part += __shfl_down_sync(0xffffffffu, part, o);
        if ((tid & 31) == 0) red[tid >> 5] = part;
        __syncthreads();
        if (tid == 0) {
            float tot = 0.0f;
#pragma unroll
            for (int w = 0; w < 8; w++) tot += red[w];
            g_IDCG[b] = fmaxf(tot, 1e-8f);
            g_SUM[b]  = 0.0f;
        }
    }
}

// grid (20, B) = 640 blocks, block 256. Two blocks per (bucket-pair, batch):
// rq in {0,1} handles row tiles i % 2 == rq. Stage both buckets once
// (sentinel-padded), loop sub-tiles with register accumulators, one atomic.
__global__ void __launch_bounds__(256) k_pairs(float* __restrict__ out, int B) {
    __shared__ float er_s[MAXPAD], sr_s[MAXPAD], dr_s[MAXPAD];
    __shared__ float ec_s[MAXPAD], dc_s[MAXPAD];
    __shared__ int   s_last;

    const int   PU[10]  = {1,2,2,3,3,3,4,4,4,4};
    const int   PV[10]  = {0,0,1,0,1,2,0,1,2,3};
    const float GAIN[5] = {0.f, 1.f, 3.f, 7.f, 15.f};

    int x   = blockIdx.x;          // 0..19
    int pi  = x >> 1;              // bucket-pair 0..9
    int rq  = x & 1;               // row-tile parity
    int b   = blockIdx.y;
    int tid = threadIdx.x;

    int lu = PU[pi], lv = PV[pi];
    int nu = g_CNT[b * 8 + lu];
    int nv = g_CNT[b * 8 + lv];
    int nut = (nu + 127) >> 7;     // row tiles

    if (nu > 0 && nv > 0 && rq < nut) {
        int offu = g_OFF[b * 8 + lu];
        int offv = g_OFF[b * 8 + lv];
        int nvt = (nv + 127) >> 7;
        int nupad = nut << 7;
        int nvpad = nvt << 7;

        // stage rows {e, s'=lg2(e), d} with high sentinel
        for (int i = tid; i < nupad; i += 256) {
            float e = E_HI, s = S_HI, d = 0.f;
            if (i < nu) {
                float2 v = g_IT[b * NMAX + offu + i];
                d = v.y;
                if (v.x != 0.f) { e = v.x; s = lg2af(v.x); }
            }
            er_s[i] = e; sr_s[i] = s; dr_s[i] = d;
        }
        // stage cols {e, d} with zero sentinel (masked cols already e=0)
        for (int i = tid; i < nvpad; i += 256) {
            float e = 0.f, d = 0.f;
            if (i < nv) {
                float2 v = g_IT[b * NMAX + offv + i];
                e = v.x; d = v.y;
            }
            ec_s[i] = e; dc_s[i] = d;
        }
        __syncthreads();

        int ty = tid >> 4, tx = tid & 15;
        float acc0 = 0.f, acc1 = 0.f, acc2 = 0.f, acc3 = 0.f;

        for (int i = rq; i < nut; i += 2) {
            int rbase = (i << 7) + ty * 8;
            float er[8], sr[8], dr[8];
#pragma unroll
            for (int k = 0; k < 8; k++) {
                er[k] = er_s[rbase + k];
                sr[k] = sr_s[rbase + k];
                dr[k] = dr_s[rbase + k];
            }
            for (int j = 0; j < nvt; j++) {
                int cbase = (j << 7) + tx * 8;
                float ec[8], dc[8];
#pragma unroll
                for (int k = 0; k < 8; k++) {
                    ec[k] = ec_s[cbase + k];
                    dc[k] = dc_s[cbase + k];
                }
#pragma unroll
                for (int a = 0; a < 8; a++) {
#pragma unroll
                    for (int c = 0; c < 8; c++) {
                        float es = er[a] + ec[c];
                        float L  = lg2af(es);
                        float t  = L - sr[a];      // softplus in log2 units (>=0)
                        float dd = dr[a] - dc[c];
                        float p  = t * dd;
                        float v  = fabsf(p);
                        switch (c & 3) {
                            case 0: acc0 += v; break;
                            case 1: acc1 += v; break;
                            case 2: acc2 += v; break;
                            default: acc3 += v; break;
                        }
                    }
                }
            }
        }

        float acc = (acc0 + acc1) + (acc2 + acc3);
#pragma unroll
        for (int o = 16; o > 0; o >>= 1) acc += __shfl_down_sync(0xffffffffu, acc, o);
        if ((tid & 31) == 0) {
            float C = GAIN[lu] - GAIN[lv];        // constant |dgain| for rectangle
            atomicAdd(&g_SUM[b], acc * C);
        }
    }

    // ---------------- Finalize (last block; no waiting, deadlock-free) ----
    if (tid == 0) {
        __threadfence();
        int old = atomicAdd(&g_FIN, 1);
        s_last = (old == (int)(gridDim.x * gridDim.y) - 1);
    }
    __syncthreads();
    if (s_last) {
        __threadfence();
        if (tid < B * 5) g_FILL[tid] = 0;         // reset for next graph replay
        if (tid < 32) {
            float v = 0.0f;
            if (tid < B)
                v = 0.6931471805599453f * atomicAdd(&g_SUM[tid], 0.0f) / g_IDCG[tid];
#pragma unroll
            for (int o = 16; o > 0; o >>= 1) v += __shfl_down_sync(0xffffffffu, v, o);
            if (tid == 0) {
                out[0] = v / (float)B;
                g_FIN = 0;
            }
        }
    }
}

extern "C" void kernel_launch(void* const* d_in, const int* in_sizes, int n_in,
                              void* d_out, int out_size) {
    const float* logits = (const float*)d_in[0];
    const float* labels = (const float*)d_in[1];
    const int*   mask   = (const int*)d_in[2];

    int B = in_sizes[0] / NMAX;
    if (B > BMAX) B = BMAX;

    dim3 gp(B, 8);
    k_prep<<<gp, 256>>>(logits, labels, mask);
    dim3 g2(20, B);
    k_pairs<<<g2, 256>>>((float*)d_out, B);
}